// round 10
// baseline (speedup 1.0000x reference)
#include <cuda_runtime.h>
#include <cstdint>

// Problem constants
#define NBATCH 2
#define NC 19
#define HWPIX (512 * 1024)         // 524288 = 2^19
#define TPIX (NBATCH * HWPIX)      // 1048576
#define LOGHW 19

// conf = max softmax prob in [1/19, 1] -> float key in [0x3D578D10, 0x3F800000]
// v = key - KBASE fits in 26 bits -> exact select in two 13-bit levels.
// Packed record: kl = (v << 5) | label
#define KBASE 0x3D000000u
#define NB0 5120
#define NB1 8192
#define VMAX  (((unsigned)NB0 << 13) - 1u)
#define R0 8
#define R1 4
#define H0_SZ (R0 * NC * NB0)      // 778240 ints
#define H1_SZ (R1 * NC * NB1)      // 622592 ints
#define HTOT (H0_SZ + H1_SZ)
#define SOLID_OFF (0x3F4CCCCDu - KBASE)   // key-offset of 0.8f

#define ADAPT_B 0.2f
#define ADAPT_A 0.9f
#define MIN_EPS 1e-8f

// Persistent-kernel geometry: 444 = 148 SMs x 3 blocks, guaranteed co-resident
// (256 thr/block, <=85 regs via launch_bounds, ~2KB smem) -> grid barrier safe.
#define GRID 444
#define TPB 256
#define NTHREADS (GRID * TPB)

// Scratch (device globals -- no allocations allowed)
__device__ unsigned int g_kl[TPIX];
__device__ float g_loss[TPIX];
__device__ int g_hist[HTOT];
__device__ int g_pfx[NC];          // selected level-0 bin
__device__ int g_rank[NC];
__device__ float g_newth[NC];
__device__ double g_num;
__device__ unsigned long long g_cm;
__device__ unsigned long long g_cs;
__device__ unsigned int g_bar_count;
__device__ volatile unsigned int g_bar_gen;

// ---------------------------------------------------------------------------
// Software grid barrier (threadfence-reduction pattern). Safe because all
// GRID blocks are co-resident by construction.
__device__ __forceinline__ void grid_sync() {
    __syncthreads();
    if (threadIdx.x == 0) {
        unsigned int gen = g_bar_gen;
        __threadfence();
        unsigned int arrived = atomicAdd(&g_bar_count, 1u) + 1u;
        if (arrived == GRID) {
            g_bar_count = 0u;
            __threadfence();
            g_bar_gen = gen + 1u;              // release
        } else {
            while (g_bar_gen == gen) __nanosleep(32);
        }
        __threadfence();                        // acquire
    }
    __syncthreads();
}

// ---------------------------------------------------------------------------
// Per-class radix-select phase (blocks 0..NC-1 only). Block-parallel suffix
// scan locates the rank-k (descending) element; threshold folded into counts.
template <int BPT, int NB, int R, int LEVEL>
__device__ __forceinline__ void select_phase(const float* __restrict__ cls_thresh,
                                             int hoff, int* s_scan)
{
    int c = blockIdx.x;
    int t = threadIdx.x;

    const int* hist = g_hist + hoff + c * NB;
    int bc[BPT];
    int csum = 0;
    int b0 = t * BPT;
#pragma unroll
    for (int i = 0; i < BPT; i++) {
        int s = 0;
        for (int r = 0; r < R; r++) s += hist[r * (NC * NB) + b0 + i];
        bc[i] = s;
        csum += s;
    }

    float thr = cls_thresh[c];
    unsigned int tk = __float_as_uint(thr);
    unsigned int tv = (tk >= KBASE) ? min(tk - KBASE, VMAX) : 0u;
    bool tin;
    int tbin;
    if (LEVEL == 0) { tin = true; tbin = (int)(tv >> 13); }
    else { tin = ((int)(tv >> 13) == g_pfx[c]); tbin = (int)(tv & (NB1 - 1)); }
    if (tin && tbin >= b0 && tbin < b0 + BPT) { bc[tbin - b0]++; csum++; }

    s_scan[t] = csum;
    __syncthreads();
    // inclusive suffix sum: s_scan[t] = sum of chunks >= t
    for (int off = 1; off < 256; off <<= 1) {
        int v = s_scan[t];
        int add = (t + off < 256) ? s_scan[t + off] : 0;
        __syncthreads();
        s_scan[t] = v + add;
        __syncthreads();
    }

    int k;
    if (LEVEL == 0) {
        int total = s_scan[0];               // == count+1 (threshold folded in)
        float t8 = powf(thr, 8.0f);
        k = (int)floorf((float)total * ADAPT_B * t8);
    } else {
        k = g_rank[c];
    }

    int hi = s_scan[t] - csum;               // sum of chunks strictly above
    if (k >= hi && k < hi + csum) {          // exactly one thread wins
        int cum = hi, selBin = 0, rankIn = 0;
#pragma unroll
        for (int i = BPT - 1; i >= 0; i--) {
            if (cum + bc[i] > k) { selBin = b0 + i; rankIn = k - cum; break; }
            cum += bc[i];
        }
        if (LEVEL == 0) {
            g_pfx[c] = selBin;
            g_rank[c] = rankIn;
        } else {
            unsigned int key = KBASE + ((unsigned)g_pfx[c] << 13) + (unsigned)selBin;
            float tmp = __uint_as_float(key);          // exact srt[idx]
            float nt = ADAPT_A * thr + (1.0f - ADAPT_A) * tmp;
            if (nt >= 1.0f) nt = 0.999f;
            g_newth[c] = nt;
        }
    }
    __syncthreads();
}

// ---------------------------------------------------------------------------
// The whole pipeline as ONE persistent kernel with 5 grid barriers.
__global__ __launch_bounds__(TPB, 3) void fused_kernel(
    const float* __restrict__ lb, const float* __restrict__ la,
    const float* __restrict__ ct, float* __restrict__ out, int out_size)
{
    __shared__ int s_scan[256];
    __shared__ int s_pfx[NC];
    __shared__ unsigned int s_th[NC];
    __shared__ float s_num[8];
    __shared__ int s_cm[8], s_cs[8];

    const int tid = blockIdx.x * TPB + threadIdx.x;

    // ---- Phase 0: zero histograms + scalars ----
    for (int i = tid * 4; i < HTOT; i += NTHREADS * 4)
        *(int4*)&g_hist[i] = make_int4(0, 0, 0, 0);
    if (tid == 0) { g_num = 0.0; g_cm = 0ull; g_cs = 0ull; }
    grid_sync();

    // ---- Phase 1: pass1 (max-free softmax, 2 px/thread, grid-stride) ----
    for (int q = tid; q < TPIX / 2; q += NTHREADS) {
        int p = q * 2;
        int n = p >> LOGHW;
        int hw = p & (HWPIX - 1);
        const float* bp = lb + (size_t)n * NC * HWPIX + hw;
        const float* ap = la + (size_t)n * NC * HWPIX + hw;

        float2 rb[NC];
#pragma unroll
        for (int c = 0; c < NC; c++)
            rb[c] = *(const float2*)(bp + (size_t)c * HWPIX);

        float mb0 = rb[0].x, mb1 = rb[0].y;
        int a0 = 0, a1 = 0;
#pragma unroll
        for (int c = 1; c < NC; c++) {
            if (rb[c].x > mb0) { mb0 = rb[c].x; a0 = c; }
            if (rb[c].y > mb1) { mb1 = rb[c].y; a1 = c; }
        }

        float Sb0 = 0.f, Sb1 = 0.f, dot0 = 0.f, dot1 = 0.f;
        float Sa0 = 0.f, Sa1 = 0.f, le0 = 0.f, le1 = 0.f;
#pragma unroll
        for (int c = 0; c < NC; c++) {
            float2 a = *(const float2*)(ap + (size_t)c * HWPIX);
            float eb0 = __expf(rb[c].x);
            float eb1 = __expf(rb[c].y);
            Sb0 += eb0; Sb1 += eb1;
            dot0 = fmaf(eb0, a.x, dot0);
            dot1 = fmaf(eb1, a.y, dot1);
            float ea0 = __expf(a.x);
            float ea1 = __expf(a.y);
            Sa0 += ea0; Sa1 += ea1;
            le0 = (c == a0) ? ea0 : le0;
            le1 = (c == a1) ? ea1 : le1;
        }

        float conf0 = __fdividef(__expf(mb0), Sb0);
        float conf1 = __fdividef(__expf(mb1), Sb1);
        float w0 = 1.0f - __fdividef(le0, Sa0);
        float w1 = 1.0f - __fdividef(le1, Sa1);
        float ce0 = __logf(Sa0) - __fdividef(dot0, Sb0);
        float ce1 = __logf(Sa1) - __fdividef(dot1, Sb1);

        unsigned int v0 = min(__float_as_uint(conf0) - KBASE, VMAX);
        unsigned int v1 = min(__float_as_uint(conf1) - KBASE, VMAX);
        ((uint2*)g_kl)[q] = make_uint2((v0 << 5) | (unsigned)a0,
                                       (v1 << 5) | (unsigned)a1);
        ((float2*)g_loss)[q] = make_float2(w0 * ce0, w1 * ce1);

        int rep = blockIdx.x & (R0 - 1);
        int* h0 = g_hist + rep * (NC * NB0);
        atomicAdd(&h0[a0 * NB0 + (int)(v0 >> 13)], 1);
        atomicAdd(&h0[a1 * NB0 + (int)(v1 >> 13)], 1);
    }
    grid_sync();

    // ---- Phase 2: level-0 select (blocks 0..18) ----
    if (blockIdx.x < NC)
        select_phase<NB0 / 256, NB0, R0, 0>(ct, 0, s_scan);
    grid_sync();

    // ---- Phase 3: level-1 fill (grid-stride over quads) ----
    if (threadIdx.x < NC) s_pfx[threadIdx.x] = g_pfx[threadIdx.x];
    __syncthreads();
    {
        int rep = blockIdx.x & (R1 - 1);
        int* h = g_hist + H0_SZ + rep * (NC * NB1);
        for (int i = tid; i < TPIX / 4; i += NTHREADS) {
            uint4 k4 = ((const uint4*)g_kl)[i];
            unsigned int ks[4] = {k4.x, k4.y, k4.z, k4.w};
#pragma unroll
            for (int j = 0; j < 4; j++) {
                int c = (int)(ks[j] & 31u);
                unsigned int v = ks[j] >> 5;
                if ((int)(v >> 13) == s_pfx[c])
                    atomicAdd(&h[c * NB1 + (int)(v & (NB1 - 1))], 1);
            }
        }
    }
    grid_sync();

    // ---- Phase 4: level-1 select (blocks 0..18) ----
    if (blockIdx.x < NC)
        select_phase<NB1 / 256, NB1, R1, 1>(ct, H0_SZ, s_scan);
    grid_sync();

    // ---- Phase 5: masked reduction ----
    if (threadIdx.x < NC)
        s_th[threadIdx.x] = __float_as_uint(g_newth[threadIdx.x]) - KBASE;
    __syncthreads();
    {
        float num = 0.f;
        int cm = 0, cs = 0;
        for (int i = tid; i < TPIX / 4; i += NTHREADS) {
            uint4 k4 = ((const uint4*)g_kl)[i];
            float4 v4 = ((const float4*)g_loss)[i];
            unsigned int ks[4] = {k4.x, k4.y, k4.z, k4.w};
            float vs[4] = {v4.x, v4.y, v4.z, v4.w};
#pragma unroll
            for (int j = 0; j < 4; j++) {
                unsigned int v = ks[j] >> 5;
                int c = (int)(ks[j] & 31u);
                if (v > s_th[c]) { num += fmaxf(vs[j], MIN_EPS); cm++; }
                if (v > SOLID_OFF) cs++;
            }
        }
        for (int o = 16; o > 0; o >>= 1) {
            num += __shfl_down_sync(0xffffffffu, num, o);
            cm  += __shfl_down_sync(0xffffffffu, cm, o);
            cs  += __shfl_down_sync(0xffffffffu, cs, o);
        }
        int wid = threadIdx.x >> 5, lid = threadIdx.x & 31;
        if (lid == 0) { s_num[wid] = num; s_cm[wid] = cm; s_cs[wid] = cs; }
        __syncthreads();
        if (wid == 0) {
            num = (lid < 8) ? s_num[lid] : 0.f;
            cm  = (lid < 8) ? s_cm[lid] : 0;
            cs  = (lid < 8) ? s_cs[lid] : 0;
            for (int o = 4; o > 0; o >>= 1) {
                num += __shfl_down_sync(0xffffffffu, num, o);
                cm  += __shfl_down_sync(0xffffffffu, cm, o);
                cs  += __shfl_down_sync(0xffffffffu, cs, o);
            }
            if (lid == 0) {
                atomicAdd(&g_num, (double)num);
                atomicAdd(&g_cm, (unsigned long long)cm);
                atomicAdd(&g_cs, (unsigned long long)cs);
            }
        }
    }
    grid_sync();

    // ---- Finalize ----
    if (tid == 0) {
        double den = (g_cm > 0ull) ? (double)g_cm : 1.0;
        if (out_size > 0) out[0] = (float)(g_num / den);
        if (out_size > 1) out[1] = (float)((double)g_cm / (double)TPIX);
        if (out_size > 2) out[2] = (float)((double)g_cs / (double)TPIX);
    }
}

// ---------------------------------------------------------------------------
extern "C" void kernel_launch(void* const* d_in, const int* in_sizes, int n_in,
                              void* d_out, int out_size)
{
    const float* lb = (const float*)d_in[0];
    const float* la = (const float*)d_in[1];
    const float* ct = (const float*)d_in[2];
    float* out = (float*)d_out;

    fused_kernel<<<GRID, TPB>>>(lb, la, ct, out, out_size);
}

// round 12
// speedup vs baseline: 1.0891x; 1.0891x over previous
#include <cuda_runtime.h>
#include <cstdint>

// Problem constants
#define NBATCH 2
#define NC 19
#define HWPIX (512 * 1024)         // 524288 = 2^19
#define TPIX (NBATCH * HWPIX)      // 1048576
#define LOGHW 19

// conf = max softmax prob in [1/19, 1] -> float key in [0x3D578D10, 0x3F800000]
// v = key - KBASE fits in 26 bits -> exact select in two 13-bit levels.
// Packed record: kl = (v << 5) | label
#define KBASE 0x3D000000u
#define NB0 5120
#define NB1 8192
#define VMAX  (((unsigned)NB0 << 13) - 1u)
#define R0 8
#define R1 4
#define H0_SZ (R0 * NC * NB0)      // 778240 ints
#define H1_SZ (R1 * NC * NB1)      // 622592 ints
#define HTOT (H0_SZ + H1_SZ)
#define SOLID_OFF (0x3F4CCCCDu - KBASE)   // key-offset of 0.8f

#define ADAPT_B 0.2f
#define ADAPT_A 0.9f
#define MIN_EPS 1e-8f

#define TPB 256
// Tail persistent kernel: 592 = 148 SMs x 4 blocks, co-resident by
// construction (launch_bounds(256,4) -> <=64 regs, tiny smem).
#define GRID2 592
#define NT2 (GRID2 * TPB)

// Scratch (device globals -- no allocations allowed).
// INVARIANT: g_hist / g_num / g_cm / g_cs are ZERO on entry to kernel_launch
// (zero-initialized at load; tail kernel re-zeroes them after finalize).
__device__ unsigned int g_kl[TPIX];
__device__ float g_loss[TPIX];
__device__ int g_hist[HTOT];
__device__ int g_pfx[NC];          // selected level-0 bin
__device__ int g_rank[NC];
__device__ float g_newth[NC];
__device__ double g_num;
__device__ unsigned long long g_cm;
__device__ unsigned long long g_cs;
__device__ unsigned int g_bar_count;
__device__ volatile unsigned int g_bar_gen;

// ---------------------------------------------------------------------------
// Pass 1 (standalone): 2 px/thread, max-free softmax. Proven config.
__global__ __launch_bounds__(256) void pass1_kernel(
    const float* __restrict__ lb, const float* __restrict__ la)
{
    int q = blockIdx.x * 256 + threadIdx.x;   // pair index; grid covers TPIX/2
    int p = q * 2;
    int n = p >> LOGHW;
    int hw = p & (HWPIX - 1);
    const float* bp = lb + (size_t)n * NC * HWPIX + hw;
    const float* ap = la + (size_t)n * NC * HWPIX + hw;

    float2 rb[NC];
#pragma unroll
    for (int c = 0; c < NC; c++)
        rb[c] = *(const float2*)(bp + (size_t)c * HWPIX);

    float mb0 = rb[0].x, mb1 = rb[0].y;
    int a0 = 0, a1 = 0;
#pragma unroll
    for (int c = 1; c < NC; c++) {
        if (rb[c].x > mb0) { mb0 = rb[c].x; a0 = c; }
        if (rb[c].y > mb1) { mb1 = rb[c].y; a1 = c; }
    }

    float Sb0 = 0.f, Sb1 = 0.f, dot0 = 0.f, dot1 = 0.f;
    float Sa0 = 0.f, Sa1 = 0.f, le0 = 0.f, le1 = 0.f;
#pragma unroll
    for (int c = 0; c < NC; c++) {
        float2 a = *(const float2*)(ap + (size_t)c * HWPIX);
        float eb0 = __expf(rb[c].x);
        float eb1 = __expf(rb[c].y);
        Sb0 += eb0; Sb1 += eb1;
        dot0 = fmaf(eb0, a.x, dot0);
        dot1 = fmaf(eb1, a.y, dot1);
        float ea0 = __expf(a.x);
        float ea1 = __expf(a.y);
        Sa0 += ea0; Sa1 += ea1;
        le0 = (c == a0) ? ea0 : le0;
        le1 = (c == a1) ? ea1 : le1;
    }

    float conf0 = __fdividef(__expf(mb0), Sb0);
    float conf1 = __fdividef(__expf(mb1), Sb1);
    float w0 = 1.0f - __fdividef(le0, Sa0);
    float w1 = 1.0f - __fdividef(le1, Sa1);
    float ce0 = __logf(Sa0) - __fdividef(dot0, Sb0);
    float ce1 = __logf(Sa1) - __fdividef(dot1, Sb1);

    unsigned int v0 = min(__float_as_uint(conf0) - KBASE, VMAX);
    unsigned int v1 = min(__float_as_uint(conf1) - KBASE, VMAX);
    ((uint2*)g_kl)[q] = make_uint2((v0 << 5) | (unsigned)a0,
                                   (v1 << 5) | (unsigned)a1);
    ((float2*)g_loss)[q] = make_float2(w0 * ce0, w1 * ce1);

    int rep = blockIdx.x & (R0 - 1);
    int* h0 = g_hist + rep * (NC * NB0);
    atomicAdd(&h0[a0 * NB0 + (int)(v0 >> 13)], 1);
    atomicAdd(&h0[a1 * NB0 + (int)(v1 >> 13)], 1);
}

// ---------------------------------------------------------------------------
// Software grid barrier for the tail kernel (co-resident by construction).
__device__ __forceinline__ void grid_sync2() {
    __syncthreads();
    if (threadIdx.x == 0) {
        unsigned int gen = g_bar_gen;
        __threadfence();
        unsigned int arrived = atomicAdd(&g_bar_count, 1u) + 1u;
        if (arrived == GRID2) {
            g_bar_count = 0u;
            __threadfence();
            g_bar_gen = gen + 1u;              // release
        } else {
            while (g_bar_gen == gen) __nanosleep(32);
        }
        __threadfence();                        // acquire
    }
    __syncthreads();
}

// ---------------------------------------------------------------------------
// Per-class radix-select phase (blocks 0..NC-1). Block-parallel suffix scan.
template <int BPT, int NB, int R, int LEVEL>
__device__ __forceinline__ void select_phase(const float* __restrict__ cls_thresh,
                                             int hoff, int* s_scan)
{
    int c = blockIdx.x;
    int t = threadIdx.x;

    const int* hist = g_hist + hoff + c * NB;
    int bc[BPT];
    int csum = 0;
    int b0 = t * BPT;
#pragma unroll
    for (int i = 0; i < BPT; i++) {
        int s = 0;
        for (int r = 0; r < R; r++) s += hist[r * (NC * NB) + b0 + i];
        bc[i] = s;
        csum += s;
    }

    float thr = cls_thresh[c];
    unsigned int tk = __float_as_uint(thr);
    unsigned int tv = (tk >= KBASE) ? min(tk - KBASE, VMAX) : 0u;
    bool tin;
    int tbin;
    if (LEVEL == 0) { tin = true; tbin = (int)(tv >> 13); }
    else { tin = ((int)(tv >> 13) == g_pfx[c]); tbin = (int)(tv & (NB1 - 1)); }
    if (tin && tbin >= b0 && tbin < b0 + BPT) { bc[tbin - b0]++; csum++; }

    s_scan[t] = csum;
    __syncthreads();
    for (int off = 1; off < 256; off <<= 1) {
        int v = s_scan[t];
        int add = (t + off < 256) ? s_scan[t + off] : 0;
        __syncthreads();
        s_scan[t] = v + add;
        __syncthreads();
    }

    int k;
    if (LEVEL == 0) {
        int total = s_scan[0];               // == count+1 (threshold folded in)
        float t8 = powf(thr, 8.0f);
        k = (int)floorf((float)total * ADAPT_B * t8);
    } else {
        k = g_rank[c];
    }

    int hi = s_scan[t] - csum;               // sum of chunks strictly above
    if (k >= hi && k < hi + csum) {          // exactly one thread wins
        int cum = hi, selBin = 0, rankIn = 0;
#pragma unroll
        for (int i = BPT - 1; i >= 0; i--) {
            if (cum + bc[i] > k) { selBin = b0 + i; rankIn = k - cum; break; }
            cum += bc[i];
        }
        if (LEVEL == 0) {
            g_pfx[c] = selBin;
            g_rank[c] = rankIn;
        } else {
            unsigned int key = KBASE + ((unsigned)g_pfx[c] << 13) + (unsigned)selBin;
            float tmp = __uint_as_float(key);          // exact srt[idx]
            float nt = ADAPT_A * thr + (1.0f - ADAPT_A) * tmp;
            if (nt >= 1.0f) nt = 0.999f;
            g_newth[c] = nt;
        }
    }
    __syncthreads();
}

// ---------------------------------------------------------------------------
// Tail: select0 -> fill1 -> select1 -> reduce -> finalize -> re-zero state.
__global__ __launch_bounds__(TPB, 4) void tail_kernel(
    const float* __restrict__ ct, float* __restrict__ out, int out_size)
{
    __shared__ int s_scan[256];
    __shared__ int s_pfx[NC];
    __shared__ unsigned int s_th[NC];
    __shared__ float s_num[8];
    __shared__ int s_cm[8], s_cs[8];

    const int tid = blockIdx.x * TPB + threadIdx.x;

    // ---- select level 0 ----
    if (blockIdx.x < NC)
        select_phase<NB0 / 256, NB0, R0, 0>(ct, 0, s_scan);
    grid_sync2();

    // ---- fill level 1 ----
    if (threadIdx.x < NC) s_pfx[threadIdx.x] = g_pfx[threadIdx.x];
    __syncthreads();
    {
        int rep = blockIdx.x & (R1 - 1);
        int* h = g_hist + H0_SZ + rep * (NC * NB1);
        for (int i = tid; i < TPIX / 4; i += NT2) {
            uint4 k4 = ((const uint4*)g_kl)[i];
            unsigned int ks[4] = {k4.x, k4.y, k4.z, k4.w};
#pragma unroll
            for (int j = 0; j < 4; j++) {
                int c = (int)(ks[j] & 31u);
                unsigned int v = ks[j] >> 5;
                if ((int)(v >> 13) == s_pfx[c])
                    atomicAdd(&h[c * NB1 + (int)(v & (NB1 - 1))], 1);
            }
        }
    }
    grid_sync2();

    // ---- select level 1 ----
    if (blockIdx.x < NC)
        select_phase<NB1 / 256, NB1, R1, 1>(ct, H0_SZ, s_scan);
    grid_sync2();

    // ---- masked reduction ----
    if (threadIdx.x < NC)
        s_th[threadIdx.x] = __float_as_uint(g_newth[threadIdx.x]) - KBASE;
    __syncthreads();
    {
        float num = 0.f;
        int cm = 0, cs = 0;
        for (int i = tid; i < TPIX / 4; i += NT2) {
            uint4 k4 = ((const uint4*)g_kl)[i];
            float4 v4 = ((const float4*)g_loss)[i];
            unsigned int ks[4] = {k4.x, k4.y, k4.z, k4.w};
            float vs[4] = {v4.x, v4.y, v4.z, v4.w};
#pragma unroll
            for (int j = 0; j < 4; j++) {
                unsigned int v = ks[j] >> 5;
                int c = (int)(ks[j] & 31u);
                if (v > s_th[c]) { num += fmaxf(vs[j], MIN_EPS); cm++; }
                if (v > SOLID_OFF) cs++;
            }
        }
        for (int o = 16; o > 0; o >>= 1) {
            num += __shfl_down_sync(0xffffffffu, num, o);
            cm  += __shfl_down_sync(0xffffffffu, cm, o);
            cs  += __shfl_down_sync(0xffffffffu, cs, o);
        }
        int wid = threadIdx.x >> 5, lid = threadIdx.x & 31;
        if (lid == 0) { s_num[wid] = num; s_cm[wid] = cm; s_cs[wid] = cs; }
        __syncthreads();
        if (wid == 0) {
            num = (lid < 8) ? s_num[lid] : 0.f;
            cm  = (lid < 8) ? s_cm[lid] : 0;
            cs  = (lid < 8) ? s_cs[lid] : 0;
            for (int o = 4; o > 0; o >>= 1) {
                num += __shfl_down_sync(0xffffffffu, num, o);
                cm  += __shfl_down_sync(0xffffffffu, cm, o);
                cs  += __shfl_down_sync(0xffffffffu, cs, o);
            }
            if (lid == 0) {
                atomicAdd(&g_num, (double)num);
                atomicAdd(&g_cm, (unsigned long long)cm);
                atomicAdd(&g_cs, (unsigned long long)cs);
            }
        }
    }
    grid_sync2();

    // ---- finalize ----
    if (tid == 0) {
        double den = (g_cm > 0ull) ? (double)g_cm : 1.0;
        if (out_size > 0) out[0] = (float)(g_num / den);
        if (out_size > 1) out[1] = (float)((double)g_cm / (double)TPIX);
        if (out_size > 2) out[2] = (float)((double)g_cs / (double)TPIX);
    }

    // ---- re-zero state for the next invocation (restores the invariant) ----
    for (int i = tid * 4; i < HTOT; i += NT2 * 4)
        *(int4*)&g_hist[i] = make_int4(0, 0, 0, 0);
    if (tid == 1) { g_num = 0.0; g_cm = 0ull; g_cs = 0ull; }
}

// ---------------------------------------------------------------------------
extern "C" void kernel_launch(void* const* d_in, const int* in_sizes, int n_in,
                              void* d_out, int out_size)
{
    const float* lb = (const float*)d_in[0];
    const float* la = (const float*)d_in[1];
    const float* ct = (const float*)d_in[2];
    float* out = (float*)d_out;

    pass1_kernel<<<TPIX / 2 / 256, 256>>>(lb, la);
    tail_kernel<<<GRID2, TPB>>>(ct, out, out_size);
}

// round 13
// speedup vs baseline: 1.4018x; 1.2871x over previous
#include <cuda_runtime.h>
#include <cstdint>

// Problem constants
#define NBATCH 2
#define NC 19
#define HWPIX (512 * 1024)         // 524288 = 2^19
#define TPIX (NBATCH * HWPIX)      // 1048576
#define LOGHW 19

// conf = max softmax prob in [1/19, 1] -> float key in [0x3D578D10, 0x3F800000]
// v = key - KBASE < 0x2800000 (2^25.3). Packed record: kl = (v << 5) | label.
// Single-level quantile histogram: bin = v >> 11 (2048-ulp bins, 20480 bins).
// tmp approx error <= 2048 ulps (~1.2e-4 in conf) -> new_thresh err <= 1.2e-5,
// far inside the 1e-3 output tolerance.
#define KBASE 0x3D000000u
#define VMAX  ((20480u << 11) - 1u)
#define NBQ 20480                  // bins per class
#define BPQ (NBQ / 256)            // 80 bins per thread in select
#define RQ 2                       // histogram replicas
#define HQ_HALF (NC * NBQ)         // 389120
#define HQ_SZ (RQ * NC * NBQ)      // 778240 ints (~3.1 MB)
#define SOLID_OFF (0x3F4CCCCDu - KBASE)   // key-offset of 0.8f

#define ADAPT_B 0.2f
#define ADAPT_A 0.9f
#define MIN_EPS 1e-8f

#define RGRID 1024                 // reduce grid

// Scratch (device globals -- no allocations allowed).
// INVARIANT: g_hist / g_num / g_cm / g_cs / g_done are ZERO on entry
// (zero-initialized at load; reduce kernel restores after finalize).
__device__ unsigned int g_kl[TPIX];
__device__ float g_loss[TPIX];
__device__ int g_hist[HQ_SZ];
__device__ float g_newth[NC];
__device__ double g_num;
__device__ unsigned long long g_cm;
__device__ unsigned long long g_cs;
__device__ unsigned int g_done;

// ---------------------------------------------------------------------------
// Pass 1: 2 px/thread, max-free softmax (proven 28us config). Histogram is
// now single-level: bin = v >> 11, two replicas selected by blockIdx parity.
__global__ __launch_bounds__(256) void pass1_kernel(
    const float* __restrict__ lb, const float* __restrict__ la)
{
    int q = blockIdx.x * 256 + threadIdx.x;   // pair index; grid covers TPIX/2
    int p = q * 2;
    int n = p >> LOGHW;
    int hw = p & (HWPIX - 1);
    const float* bp = lb + (size_t)n * NC * HWPIX + hw;
    const float* ap = la + (size_t)n * NC * HWPIX + hw;

    float2 rb[NC];
#pragma unroll
    for (int c = 0; c < NC; c++)
        rb[c] = *(const float2*)(bp + (size_t)c * HWPIX);

    float mb0 = rb[0].x, mb1 = rb[0].y;
    int a0 = 0, a1 = 0;
#pragma unroll
    for (int c = 1; c < NC; c++) {
        if (rb[c].x > mb0) { mb0 = rb[c].x; a0 = c; }
        if (rb[c].y > mb1) { mb1 = rb[c].y; a1 = c; }
    }

    float Sb0 = 0.f, Sb1 = 0.f, dot0 = 0.f, dot1 = 0.f;
    float Sa0 = 0.f, Sa1 = 0.f, le0 = 0.f, le1 = 0.f;
#pragma unroll
    for (int c = 0; c < NC; c++) {
        float2 a = *(const float2*)(ap + (size_t)c * HWPIX);
        float eb0 = __expf(rb[c].x);
        float eb1 = __expf(rb[c].y);
        Sb0 += eb0; Sb1 += eb1;
        dot0 = fmaf(eb0, a.x, dot0);
        dot1 = fmaf(eb1, a.y, dot1);
        float ea0 = __expf(a.x);
        float ea1 = __expf(a.y);
        Sa0 += ea0; Sa1 += ea1;
        le0 = (c == a0) ? ea0 : le0;
        le1 = (c == a1) ? ea1 : le1;
    }

    float conf0 = __fdividef(__expf(mb0), Sb0);
    float conf1 = __fdividef(__expf(mb1), Sb1);
    float w0 = 1.0f - __fdividef(le0, Sa0);
    float w1 = 1.0f - __fdividef(le1, Sa1);
    float ce0 = __logf(Sa0) - __fdividef(dot0, Sb0);
    float ce1 = __logf(Sa1) - __fdividef(dot1, Sb1);

    unsigned int v0 = min(__float_as_uint(conf0) - KBASE, VMAX);
    unsigned int v1 = min(__float_as_uint(conf1) - KBASE, VMAX);
    ((uint2*)g_kl)[q] = make_uint2((v0 << 5) | (unsigned)a0,
                                   (v1 << 5) | (unsigned)a1);
    ((float2*)g_loss)[q] = make_float2(w0 * ce0, w1 * ce1);

    int* h0 = g_hist + (blockIdx.x & (RQ - 1)) * HQ_HALF;
    atomicAdd(&h0[a0 * NBQ + (int)(v0 >> 11)], 1);
    atomicAdd(&h0[a1 * NBQ + (int)(v1 >> 11)], 1);
}

// ---------------------------------------------------------------------------
// Single-level quantile select: one block per class. Two-stage block-parallel
// suffix scan (80-bin chunks -> winning chunk's bins). The appended threshold
// element is folded into the counts. tmp := lower edge of the rank-k bin.
__global__ void selectq_kernel(const float* __restrict__ cls_thresh)
{
    int c = blockIdx.x;
    int t = threadIdx.x;
    __shared__ int s_scan[256];
    __shared__ int s_win[2];           // winning chunk, rank within chunk

    const int* hist = g_hist + c * NBQ;
    float thr = cls_thresh[c];
    unsigned int tk = __float_as_uint(thr);
    unsigned int tv = (tk >= KBASE) ? min(tk - KBASE, VMAX) : 0u;
    int tbin = (int)(tv >> 11);

    // Stage A: chunk sums (80 bins x 2 replicas each)
    int b0 = t * BPQ;
    int csum = 0;
#pragma unroll 4
    for (int i = 0; i < BPQ; i++)
        csum += hist[b0 + i] + hist[HQ_HALF + b0 + i];
    if (tbin >= b0 && tbin < b0 + BPQ) csum++;          // fold threshold elem

    s_scan[t] = csum;
    __syncthreads();
    for (int off = 1; off < 256; off <<= 1) {           // suffix sum
        int v = s_scan[t];
        int add = (t + off < 256) ? s_scan[t + off] : 0;
        __syncthreads();
        s_scan[t] = v + add;
        __syncthreads();
    }

    int total = s_scan[0];                               // == count + 1
    int k = (int)floorf((float)total * ADAPT_B * powf(thr, 8.0f));
    int hi = s_scan[t] - csum;                           // strictly above
    if (k >= hi && k < hi + csum) { s_win[0] = t; s_win[1] = k - hi; }
    __syncthreads();

    // Stage B: scan the winning chunk's 80 bins
    int wc = s_win[0], kk = s_win[1];
    int bin = wc * BPQ + t;
    int bc = 0;
    if (t < BPQ) {
        bc = hist[bin] + hist[HQ_HALF + bin];
        if (tbin == bin) bc++;
    }
    __syncthreads();
    s_scan[t] = bc;
    __syncthreads();
    for (int off = 1; off < 256; off <<= 1) {
        int v = s_scan[t];
        int add = (t + off < 256) ? s_scan[t + off] : 0;
        __syncthreads();
        s_scan[t] = v + add;
        __syncthreads();
    }
    hi = s_scan[t] - bc;
    if (t < BPQ && kk >= hi && kk < hi + bc) {           // exactly one wins
        unsigned int key = KBASE + ((unsigned)bin << 11);
        float tmp = __uint_as_float(key);                // bin lower edge
        float nt = ADAPT_A * thr + (1.0f - ADAPT_A) * tmp;
        if (nt >= 1.0f) nt = 0.999f;
        g_newth[c] = nt;
    }
}

// ---------------------------------------------------------------------------
// Masked reduction + finalize (done-counter) + state rezero for next run.
__global__ __launch_bounds__(256) void reduce_kernel(float* __restrict__ out,
                                                     int out_size) {
    __shared__ unsigned int s_th[NC];      // threshold in key-offset space
    if (threadIdx.x < NC)
        s_th[threadIdx.x] = __float_as_uint(g_newth[threadIdx.x]) - KBASE;
    __syncthreads();
    int stride = gridDim.x * blockDim.x;
    int tid = blockIdx.x * blockDim.x + threadIdx.x;
    float num = 0.f;
    int cm = 0, cs = 0;
    for (int i = tid; i < TPIX / 4; i += stride) {
        uint4 k4 = ((const uint4*)g_kl)[i];
        float4 v4 = ((const float4*)g_loss)[i];
        unsigned int ks[4] = {k4.x, k4.y, k4.z, k4.w};
        float vs[4] = {v4.x, v4.y, v4.z, v4.w};
#pragma unroll
        for (int j = 0; j < 4; j++) {
            unsigned int v = ks[j] >> 5;
            int c = (int)(ks[j] & 31u);
            if (v > s_th[c]) { num += fmaxf(vs[j], MIN_EPS); cm++; }
            if (v > SOLID_OFF) cs++;
        }
    }
    // re-zero this block's slice of the histogram (not used by this kernel)
    for (int i = tid * 4; i < HQ_SZ; i += stride * 4)
        *(int4*)&g_hist[i] = make_int4(0, 0, 0, 0);

    for (int o = 16; o > 0; o >>= 1) {
        num += __shfl_down_sync(0xffffffffu, num, o);
        cm  += __shfl_down_sync(0xffffffffu, cm, o);
        cs  += __shfl_down_sync(0xffffffffu, cs, o);
    }
    __shared__ float s_num[8];
    __shared__ int s_cm[8], s_cs[8];
    int wid = threadIdx.x >> 5, lid = threadIdx.x & 31;
    if (lid == 0) { s_num[wid] = num; s_cm[wid] = cm; s_cs[wid] = cs; }
    __syncthreads();
    if (wid == 0) {
        num = (lid < 8) ? s_num[lid] : 0.f;
        cm  = (lid < 8) ? s_cm[lid] : 0;
        cs  = (lid < 8) ? s_cs[lid] : 0;
        for (int o = 4; o > 0; o >>= 1) {
            num += __shfl_down_sync(0xffffffffu, num, o);
            cm  += __shfl_down_sync(0xffffffffu, cm, o);
            cs  += __shfl_down_sync(0xffffffffu, cs, o);
        }
        if (lid == 0) {
            atomicAdd(&g_num, (double)num);
            atomicAdd(&g_cm, (unsigned long long)cm);
            atomicAdd(&g_cs, (unsigned long long)cs);
            __threadfence();
            unsigned int old = atomicAdd(&g_done, 1u);
            if (old == gridDim.x - 1) {          // last block finalizes
                double den = (g_cm > 0ull) ? (double)g_cm : 1.0;
                if (out_size > 0) out[0] = (float)(g_num / den);
                if (out_size > 1) out[1] = (float)((double)g_cm / (double)TPIX);
                if (out_size > 2) out[2] = (float)((double)g_cs / (double)TPIX);
                // restore the zero invariant for the next invocation
                g_num = 0.0; g_cm = 0ull; g_cs = 0ull;
                __threadfence();
                g_done = 0u;
            }
        }
    }
}

// ---------------------------------------------------------------------------
extern "C" void kernel_launch(void* const* d_in, const int* in_sizes, int n_in,
                              void* d_out, int out_size)
{
    const float* lb = (const float*)d_in[0];
    const float* la = (const float*)d_in[1];
    const float* ct = (const float*)d_in[2];
    float* out = (float*)d_out;

    pass1_kernel<<<TPIX / 2 / 256, 256>>>(lb, la);
    selectq_kernel<<<NC, 256>>>(ct);
    reduce_kernel<<<RGRID, 256>>>(out, out_size);
}

// round 14
// speedup vs baseline: 1.4715x; 1.0497x over previous
#include <cuda_runtime.h>
#include <cstdint>

// Problem constants
#define NBATCH 2
#define NC 19
#define HWPIX (512 * 1024)         // 524288 = 2^19
#define TPIX (NBATCH * HWPIX)      // 1048576
#define LOGHW 19

// conf = max softmax prob in [1/19, 1] -> float key in [0x3D578D10, 0x3F800000]
// v = key - KBASE < 2^25.4. Packed record: kl = (v << 5) | label.
// Single-level quantile histogram: bin = v >> 11 (2048-ulp bins, 20480 bins).
// tmp approx error <= 2048 ulps (~1.2e-4 in conf) -> new_thresh err <= 1.2e-5,
// far inside the 1e-3 output tolerance (measured rel_err 0.0).
#define KBASE 0x3D000000u
#define VMAX  ((20480u << 11) - 1u)
#define NBQ 20480                  // bins per class
#define BPQ (NBQ / 256)            // 80 bins per thread in select
#define RQ 2                       // histogram replicas
#define HQ_HALF (NC * NBQ)         // 389120
#define HQ_SZ (RQ * NC * NBQ)      // 778240 ints (~3.1 MB)
#define SOLID_OFF (0x3F4CCCCDu - KBASE)   // key-offset of 0.8f

#define ADAPT_B 0.2f
#define ADAPT_A 0.9f
#define MIN_EPS 1e-8f

#define RGRID 512                  // reduce grid (2 quads per thread)

// Scratch (device globals -- no allocations allowed).
// INVARIANT: g_hist / g_num / g_cm / g_cs / g_done are ZERO on entry
// (zero-initialized at load; reduce kernel restores after finalize).
__device__ unsigned int g_kl[TPIX];
__device__ float g_loss[TPIX];
__device__ int g_hist[HQ_SZ];
__device__ float g_newth[NC];
__device__ double g_num;
__device__ unsigned long long g_cm;
__device__ unsigned long long g_cs;
__device__ unsigned int g_done;

// ---------------------------------------------------------------------------
// Pass 1: ONE pixel/thread (low regs -> high occupancy), max-free softmax.
// Inputs loaded with __ldcs (evict-first) so the kl/loss outputs survive in
// L2 for the reduce kernel.
__global__ __launch_bounds__(256) void pass1_kernel(
    const float* __restrict__ lb, const float* __restrict__ la)
{
    int p = blockIdx.x * 256 + threadIdx.x;   // grid covers TPIX
    int n = p >> LOGHW;
    int hw = p & (HWPIX - 1);
    const float* bp = lb + (size_t)n * NC * HWPIX + hw;
    const float* ap = la + (size_t)n * NC * HWPIX + hw;

    // Load all before-logits (front-batched -> max MLP)
    float rb[NC];
#pragma unroll
    for (int c = 0; c < NC; c++)
        rb[c] = __ldcs(bp + (size_t)c * HWPIX);

    // max + argmax (first max wins, matching jnp.argmax)
    float mb = rb[0];
    int a0 = 0;
#pragma unroll
    for (int c = 1; c < NC; c++)
        if (rb[c] > mb) { mb = rb[c]; a0 = c; }

    // Stream after-logits; accumulate Sb, dot, Sa, and ea at the b-argmax.
    float Sb = 0.f, dot = 0.f, Sa = 0.f, le = 0.f;
#pragma unroll
    for (int c = 0; c < NC; c++) {
        float a = __ldcs(ap + (size_t)c * HWPIX);
        float eb = __expf(rb[c]);
        Sb += eb;
        dot = fmaf(eb, a, dot);
        float ea = __expf(a);
        Sa += ea;
        le = (c == a0) ? ea : le;
    }

    float conf = __fdividef(__expf(mb), Sb);
    float w = 1.0f - __fdividef(le, Sa);
    float ce = __logf(Sa) - __fdividef(dot, Sb);

    unsigned int v = min(__float_as_uint(conf) - KBASE, VMAX);
    g_kl[p] = (v << 5) | (unsigned)a0;
    g_loss[p] = w * ce;

    int* h0 = g_hist + (blockIdx.x & (RQ - 1)) * HQ_HALF;
    atomicAdd(&h0[a0 * NBQ + (int)(v >> 11)], 1);
}

// ---------------------------------------------------------------------------
// Single-level quantile select: one block per class. Two-stage block-parallel
// suffix scan (80-bin chunks -> winning chunk's bins). The appended threshold
// element is folded into the counts. tmp := lower edge of the rank-k bin.
__global__ void selectq_kernel(const float* __restrict__ cls_thresh)
{
    int c = blockIdx.x;
    int t = threadIdx.x;
    __shared__ int s_scan[256];
    __shared__ int s_win[2];           // winning chunk, rank within chunk

    const int* hist = g_hist + c * NBQ;
    float thr = cls_thresh[c];
    unsigned int tk = __float_as_uint(thr);
    unsigned int tv = (tk >= KBASE) ? min(tk - KBASE, VMAX) : 0u;
    int tbin = (int)(tv >> 11);

    // Stage A: chunk sums (80 bins x 2 replicas each)
    int b0 = t * BPQ;
    int csum = 0;
#pragma unroll 4
    for (int i = 0; i < BPQ; i++)
        csum += hist[b0 + i] + hist[HQ_HALF + b0 + i];
    if (tbin >= b0 && tbin < b0 + BPQ) csum++;          // fold threshold elem

    s_scan[t] = csum;
    __syncthreads();
    for (int off = 1; off < 256; off <<= 1) {           // suffix sum
        int v = s_scan[t];
        int add = (t + off < 256) ? s_scan[t + off] : 0;
        __syncthreads();
        s_scan[t] = v + add;
        __syncthreads();
    }

    int total = s_scan[0];                               // == count + 1
    int k = (int)floorf((float)total * ADAPT_B * powf(thr, 8.0f));
    int hi = s_scan[t] - csum;                           // strictly above
    if (k >= hi && k < hi + csum) { s_win[0] = t; s_win[1] = k - hi; }
    __syncthreads();

    // Stage B: scan the winning chunk's 80 bins
    int wc = s_win[0], kk = s_win[1];
    int bin = wc * BPQ + t;
    int bc = 0;
    if (t < BPQ) {
        bc = hist[bin] + hist[HQ_HALF + bin];
        if (tbin == bin) bc++;
    }
    __syncthreads();
    s_scan[t] = bc;
    __syncthreads();
    for (int off = 1; off < 256; off <<= 1) {
        int v = s_scan[t];
        int add = (t + off < 256) ? s_scan[t + off] : 0;
        __syncthreads();
        s_scan[t] = v + add;
        __syncthreads();
    }
    hi = s_scan[t] - bc;
    if (t < BPQ && kk >= hi && kk < hi + bc) {           // exactly one wins
        unsigned int key = KBASE + ((unsigned)bin << 11);
        float tmp = __uint_as_float(key);                // bin lower edge
        float nt = ADAPT_A * thr + (1.0f - ADAPT_A) * tmp;
        if (nt >= 1.0f) nt = 0.999f;
        g_newth[c] = nt;
    }
}

// ---------------------------------------------------------------------------
// Masked reduction (2 quads/thread, batched loads) + finalize + state rezero.
__global__ __launch_bounds__(256) void reduce_kernel(float* __restrict__ out,
                                                     int out_size) {
    __shared__ unsigned int s_th[NC];      // threshold in key-offset space
    if (threadIdx.x < NC)
        s_th[threadIdx.x] = __float_as_uint(g_newth[threadIdx.x]) - KBASE;
    __syncthreads();
    int tid = blockIdx.x * blockDim.x + threadIdx.x;
    int i0 = tid * 2;                      // 2 quads; RGRID*256*2 == TPIX/4
    uint4 ka = ((const uint4*)g_kl)[i0];
    uint4 kb = ((const uint4*)g_kl)[i0 + 1];
    float4 va = ((const float4*)g_loss)[i0];
    float4 vb = ((const float4*)g_loss)[i0 + 1];

    float num = 0.f;
    int cm = 0, cs = 0;
    unsigned int ks[8] = {ka.x, ka.y, ka.z, ka.w, kb.x, kb.y, kb.z, kb.w};
    float vs[8] = {va.x, va.y, va.z, va.w, vb.x, vb.y, vb.z, vb.w};
#pragma unroll
    for (int j = 0; j < 8; j++) {
        unsigned int v = ks[j] >> 5;
        int c = (int)(ks[j] & 31u);
        if (v > s_th[c]) { num += fmaxf(vs[j], MIN_EPS); cm++; }
        if (v > SOLID_OFF) cs++;
    }

    // re-zero this thread's slice of the histogram (restores the invariant)
    {
        int stride = RGRID * 256 * 4;
        for (int i = tid * 4; i < HQ_SZ; i += stride)
            *(int4*)&g_hist[i] = make_int4(0, 0, 0, 0);
    }

    for (int o = 16; o > 0; o >>= 1) {
        num += __shfl_down_sync(0xffffffffu, num, o);
        cm  += __shfl_down_sync(0xffffffffu, cm, o);
        cs  += __shfl_down_sync(0xffffffffu, cs, o);
    }
    __shared__ float s_num[8];
    __shared__ int s_cm[8], s_cs[8];
    int wid = threadIdx.x >> 5, lid = threadIdx.x & 31;
    if (lid == 0) { s_num[wid] = num; s_cm[wid] = cm; s_cs[wid] = cs; }
    __syncthreads();
    if (wid == 0) {
        num = (lid < 8) ? s_num[lid] : 0.f;
        cm  = (lid < 8) ? s_cm[lid] : 0;
        cs  = (lid < 8) ? s_cs[lid] : 0;
        for (int o = 4; o > 0; o >>= 1) {
            num += __shfl_down_sync(0xffffffffu, num, o);
            cm  += __shfl_down_sync(0xffffffffu, cm, o);
            cs  += __shfl_down_sync(0xffffffffu, cs, o);
        }
        if (lid == 0) {
            atomicAdd(&g_num, (double)num);
            atomicAdd(&g_cm, (unsigned long long)cm);
            atomicAdd(&g_cs, (unsigned long long)cs);
            __threadfence();
            unsigned int old = atomicAdd(&g_done, 1u);
            if (old == gridDim.x - 1) {          // last block finalizes
                double den = (g_cm > 0ull) ? (double)g_cm : 1.0;
                if (out_size > 0) out[0] = (float)(g_num / den);
                if (out_size > 1) out[1] = (float)((double)g_cm / (double)TPIX);
                if (out_size > 2) out[2] = (float)((double)g_cs / (double)TPIX);
                // restore the zero invariant for the next invocation
                g_num = 0.0; g_cm = 0ull; g_cs = 0ull;
                __threadfence();
                g_done = 0u;
            }
        }
    }
}

// ---------------------------------------------------------------------------
extern "C" void kernel_launch(void* const* d_in, const int* in_sizes, int n_in,
                              void* d_out, int out_size)
{
    const float* lb = (const float*)d_in[0];
    const float* la = (const float*)d_in[1];
    const float* ct = (const float*)d_in[2];
    float* out = (float*)d_out;

    pass1_kernel<<<TPIX / 256, 256>>>(lb, la);
    selectq_kernel<<<NC, 256>>>(ct);
    reduce_kernel<<<RGRID, 256>>>(out, out_size);
}

// round 15
// speedup vs baseline: 1.5189x; 1.0322x over previous
#include <cuda_runtime.h>
#include <cstdint>

// Problem constants
#define NBATCH 2
#define NC 19
#define HWPIX (512 * 1024)         // 524288 = 2^19
#define TPIX (NBATCH * HWPIX)      // 1048576
#define LOGHW 19

// conf = max softmax prob in [1/19, 1] -> float key in [0x3D578D10, 0x3F800000]
// v = key - KBASE < 2^25.4. Packed record: kl = (v << 5) | label.
// Single-level quantile histogram: bin = v >> 11 (2048-ulp bins, 20480 bins).
// tmp approx error <= 2048 ulps (~1.2e-4 in conf) -> new_thresh err <= 1.2e-5,
// far inside the 1e-3 output tolerance (measured rel_err 0.0).
#define KBASE 0x3D000000u
#define VMAX  ((20480u << 11) - 1u)
#define NBQ 20480                  // bins per class
#define BPQ (NBQ / 256)            // 80 bins per thread in select
#define RQ 2                       // histogram replicas
#define HQ_HALF (NC * NBQ)         // 389120
#define HQ_SZ (RQ * NC * NBQ)      // 778240 ints (~3.1 MB)
#define SOLID_OFF (0x3F4CCCCDu - KBASE)   // key-offset of 0.8f

#define ADAPT_B 0.2f
#define ADAPT_A 0.9f
#define MIN_EPS 1e-8f

#define RGRID 512                  // reduce grid (2 quads per thread)

// Scratch (device globals -- no allocations allowed).
// INVARIANT: g_hist / g_num / g_cm / g_cs / g_done / g_selcnt are ZERO on
// entry (zero-initialized at load; reduce kernel restores after finalize).
__device__ unsigned int g_kl[TPIX];
__device__ float g_loss[TPIX];
__device__ int g_hist[HQ_SZ];
__device__ float g_newth[NC];
__device__ double g_num;
__device__ unsigned long long g_cm;
__device__ unsigned long long g_cs;
__device__ unsigned int g_done;
__device__ unsigned int g_selcnt;

// ---------------------------------------------------------------------------
// Pass 1: ONE pixel/thread (low regs -> high occupancy), max-free softmax.
// Frozen: measured at the 5.37 TB/s pattern ceiling (DRAM 67.8%).
__global__ __launch_bounds__(256) void pass1_kernel(
    const float* __restrict__ lb, const float* __restrict__ la)
{
    int p = blockIdx.x * 256 + threadIdx.x;   // grid covers TPIX
    int n = p >> LOGHW;
    int hw = p & (HWPIX - 1);
    const float* bp = lb + (size_t)n * NC * HWPIX + hw;
    const float* ap = la + (size_t)n * NC * HWPIX + hw;

    float rb[NC];
#pragma unroll
    for (int c = 0; c < NC; c++)
        rb[c] = __ldcs(bp + (size_t)c * HWPIX);

    float mb = rb[0];
    int a0 = 0;
#pragma unroll
    for (int c = 1; c < NC; c++)
        if (rb[c] > mb) { mb = rb[c]; a0 = c; }

    float Sb = 0.f, dot = 0.f, Sa = 0.f, le = 0.f;
#pragma unroll
    for (int c = 0; c < NC; c++) {
        float a = __ldcs(ap + (size_t)c * HWPIX);
        float eb = __expf(rb[c]);
        Sb += eb;
        dot = fmaf(eb, a, dot);
        float ea = __expf(a);
        Sa += ea;
        le = (c == a0) ? ea : le;
    }

    float conf = __fdividef(__expf(mb), Sb);
    float w = 1.0f - __fdividef(le, Sa);
    float ce = __logf(Sa) - __fdividef(dot, Sb);

    unsigned int v = min(__float_as_uint(conf) - KBASE, VMAX);
    g_kl[p] = (v << 5) | (unsigned)a0;
    g_loss[p] = w * ce;

    int* h0 = g_hist + (blockIdx.x & (RQ - 1)) * HQ_HALF;
    atomicAdd(&h0[a0 * NBQ + (int)(v >> 11)], 1);
}

// ---------------------------------------------------------------------------
// Per-class quantile select (device fn, run by reduce blocks 0..18).
__device__ void selectq_class(const float* __restrict__ cls_thresh,
                              int c, int* s_scan, int* s_win)
{
    int t = threadIdx.x;
    const int* hist = g_hist + c * NBQ;
    float thr = cls_thresh[c];
    unsigned int tk = __float_as_uint(thr);
    unsigned int tv = (tk >= KBASE) ? min(tk - KBASE, VMAX) : 0u;
    int tbin = (int)(tv >> 11);

    // Stage A: chunk sums (80 bins x 2 replicas each)
    int b0 = t * BPQ;
    int csum = 0;
#pragma unroll 4
    for (int i = 0; i < BPQ; i++)
        csum += hist[b0 + i] + hist[HQ_HALF + b0 + i];
    if (tbin >= b0 && tbin < b0 + BPQ) csum++;          // fold threshold elem

    s_scan[t] = csum;
    __syncthreads();
    for (int off = 1; off < 256; off <<= 1) {           // suffix sum
        int v = s_scan[t];
        int add = (t + off < 256) ? s_scan[t + off] : 0;
        __syncthreads();
        s_scan[t] = v + add;
        __syncthreads();
    }

    int total = s_scan[0];                               // == count + 1
    int k = (int)floorf((float)total * ADAPT_B * powf(thr, 8.0f));
    int hi = s_scan[t] - csum;                           // strictly above
    if (k >= hi && k < hi + csum) { s_win[0] = t; s_win[1] = k - hi; }
    __syncthreads();

    // Stage B: scan the winning chunk's 80 bins
    int wc = s_win[0], kk = s_win[1];
    int bin = wc * BPQ + t;
    int bc = 0;
    if (t < BPQ) {
        bc = hist[bin] + hist[HQ_HALF + bin];
        if (tbin == bin) bc++;
    }
    __syncthreads();
    s_scan[t] = bc;
    __syncthreads();
    for (int off = 1; off < 256; off <<= 1) {
        int v = s_scan[t];
        int add = (t + off < 256) ? s_scan[t + off] : 0;
        __syncthreads();
        s_scan[t] = v + add;
        __syncthreads();
    }
    hi = s_scan[t] - bc;
    if (t < BPQ && kk >= hi && kk < hi + bc) {           // exactly one wins
        unsigned int key = KBASE + ((unsigned)bin << 11);
        float tmp = __uint_as_float(key);                // bin lower edge
        float nt = ADAPT_A * thr + (1.0f - ADAPT_A) * tmp;
        if (nt >= 1.0f) nt = 0.999f;
        g_newth[c] = nt;
    }
    __syncthreads();
}

// ---------------------------------------------------------------------------
// Fused select + masked reduction + finalize + state rezero.
// Blocks 0..18 run select for their class, then flag via g_selcnt.
// All blocks: issue data loads + threshold-independent work first, spin on
// the flag (sub-us; 19 producers), then apply the mask. Co-residency of all
// RGRID blocks is guaranteed (<=64 regs, 256 thr, launch_bounds(256,4)).
__global__ __launch_bounds__(256, 4) void reduce_kernel(
    const float* __restrict__ ct, float* __restrict__ out, int out_size)
{
    __shared__ int s_scan[256];
    __shared__ int s_win[2];
    __shared__ unsigned int s_th[NC];      // threshold in key-offset space

    int tid = blockIdx.x * blockDim.x + threadIdx.x;

    // ---- producer role: per-class select ----
    if (blockIdx.x < NC) {
        selectq_class(ct, blockIdx.x, s_scan, s_win);
        if (threadIdx.x == 0) {
            __threadfence();
            atomicAdd(&g_selcnt, 1u);
        }
    }

    // ---- threshold-independent work (overlaps select in other blocks) ----
    int i0 = tid * 2;                      // 2 quads; RGRID*256*2 == TPIX/4
    uint4 ka = ((const uint4*)g_kl)[i0];
    uint4 kb = ((const uint4*)g_kl)[i0 + 1];
    float4 va = ((const float4*)g_loss)[i0];
    float4 vb = ((const float4*)g_loss)[i0 + 1];
    unsigned int ks[8] = {ka.x, ka.y, ka.z, ka.w, kb.x, kb.y, kb.z, kb.w};
    float vs[8] = {va.x, va.y, va.z, va.w, vb.x, vb.y, vb.z, vb.w};

    int cs = 0;
#pragma unroll
    for (int j = 0; j < 8; j++)
        if ((ks[j] >> 5) > SOLID_OFF) cs++;

    // re-zero this thread's slice of the histogram (restores the invariant)
    // NOTE: safe concurrently with producers -- they only read hist for their
    // own class BEFORE flagging; rezero by waiters could race producers, so
    // defer hist rezero until after the spin (below).

    // ---- wait for all 19 selects ----
    if (threadIdx.x == 0) {
        while (*((volatile unsigned int*)&g_selcnt) < NC) __nanosleep(64);
    }
    __syncthreads();
    __threadfence();                        // acquire
    if (threadIdx.x < NC)
        s_th[threadIdx.x] = __float_as_uint(g_newth[threadIdx.x]) - KBASE;
    __syncthreads();

    // hist rezero (all selects done -> safe)
    {
        int stride = RGRID * 256 * 4;
        for (int i = tid * 4; i < HQ_SZ; i += stride)
            *(int4*)&g_hist[i] = make_int4(0, 0, 0, 0);
    }

    // ---- masked compute ----
    float num = 0.f;
    int cm = 0;
#pragma unroll
    for (int j = 0; j < 8; j++) {
        unsigned int v = ks[j] >> 5;
        int c = (int)(ks[j] & 31u);
        if (v > s_th[c]) { num += fmaxf(vs[j], MIN_EPS); cm++; }
    }

    for (int o = 16; o > 0; o >>= 1) {
        num += __shfl_down_sync(0xffffffffu, num, o);
        cm  += __shfl_down_sync(0xffffffffu, cm, o);
        cs  += __shfl_down_sync(0xffffffffu, cs, o);
    }
    __shared__ float s_num[8];
    __shared__ int s_cm[8], s_cs[8];
    int wid = threadIdx.x >> 5, lid = threadIdx.x & 31;
    if (lid == 0) { s_num[wid] = num; s_cm[wid] = cm; s_cs[wid] = cs; }
    __syncthreads();
    if (wid == 0) {
        num = (lid < 8) ? s_num[lid] : 0.f;
        cm  = (lid < 8) ? s_cm[lid] : 0;
        cs  = (lid < 8) ? s_cs[lid] : 0;
        for (int o = 4; o > 0; o >>= 1) {
            num += __shfl_down_sync(0xffffffffu, num, o);
            cm  += __shfl_down_sync(0xffffffffu, cm, o);
            cs  += __shfl_down_sync(0xffffffffu, cs, o);
        }
        if (lid == 0) {
            atomicAdd(&g_num, (double)num);
            atomicAdd(&g_cm, (unsigned long long)cm);
            atomicAdd(&g_cs, (unsigned long long)cs);
            __threadfence();
            unsigned int old = atomicAdd(&g_done, 1u);
            if (old == gridDim.x - 1) {          // last block finalizes
                double den = (g_cm > 0ull) ? (double)g_cm : 1.0;
                if (out_size > 0) out[0] = (float)(g_num / den);
                if (out_size > 1) out[1] = (float)((double)g_cm / (double)TPIX);
                if (out_size > 2) out[2] = (float)((double)g_cs / (double)TPIX);
                // restore the zero invariant for the next invocation
                g_num = 0.0; g_cm = 0ull; g_cs = 0ull; g_selcnt = 0u;
                __threadfence();
                g_done = 0u;
            }
        }
    }
}

// ---------------------------------------------------------------------------
extern "C" void kernel_launch(void* const* d_in, const int* in_sizes, int n_in,
                              void* d_out, int out_size)
{
    const float* lb = (const float*)d_in[0];
    const float* la = (const float*)d_in[1];
    const float* ct = (const float*)d_in[2];
    float* out = (float*)d_out;

    pass1_kernel<<<TPIX / 256, 256>>>(lb, la);
    reduce_kernel<<<RGRID, 256>>>(ct, out, out_size);
}

// round 16
// speedup vs baseline: 1.8748x; 1.2344x over previous
#include <cuda_runtime.h>
#include <cstdint>

// Problem constants
#define NBATCH 2
#define NC 19
#define HWPIX (512 * 1024)         // 524288 = 2^19
#define TPIX (NBATCH * HWPIX)      // 1048576
#define LOGHW 19

// conf = max softmax prob in [1/19, 1] -> float key in [0x3D578D10, 0x3F800000]
// v = key - KBASE < 2^25.4. Packed record: kl = (v << 5) | label.
// Quantile histogram: bin = v >> 13 (8192-ulp bins, 5120 bins/class).
// tmp approx rel-err <= ~5e-4 -> new_thresh err <= 5e-5, far inside the 1e-3
// output tolerance (4x finer bins measured rel_err 0.0).
#define KBASE 0x3D000000u
#define NBQ 5120                   // bins per class
#define BPQ (NBQ / 256)            // 20 bins per thread in select
#define RQ 4                       // histogram replicas
#define VMAX  (((unsigned)NBQ << 13) - 1u)
#define HQ_CLS (NC * NBQ)          // 97280
#define HQ_SZ (RQ * HQ_CLS)        // 389120 ints (~1.5 MB)
#define SOLID_OFF (0x3F4CCCCDu - KBASE)   // key-offset of 0.8f

#define ADAPT_B 0.2f
#define ADAPT_A 0.9f
#define MIN_EPS 1e-8f

#define RGRID 512                  // reduce grid (2 quads per thread)

// Scratch (device globals -- no allocations allowed).
// INVARIANT: g_hist / g_num / g_cm / g_cs / g_done / g_selcnt are ZERO on
// entry (zero-initialized at load; reduce kernel restores after finalize).
__device__ unsigned int g_kl[TPIX];
__device__ float g_loss[TPIX];
__device__ int g_hist[HQ_SZ];
__device__ float g_newth[NC];
__device__ double g_num;
__device__ unsigned long long g_cm;
__device__ unsigned long long g_cs;
__device__ unsigned int g_done;
__device__ unsigned int g_selcnt;

// ---------------------------------------------------------------------------
// Pass 1: ONE pixel/thread (low regs -> high occupancy), max-free softmax.
// Frozen: measured at the 5.37 TB/s pattern ceiling (DRAM 67.8%).
__global__ __launch_bounds__(256) void pass1_kernel(
    const float* __restrict__ lb, const float* __restrict__ la)
{
    int p = blockIdx.x * 256 + threadIdx.x;   // grid covers TPIX
    int n = p >> LOGHW;
    int hw = p & (HWPIX - 1);
    const float* bp = lb + (size_t)n * NC * HWPIX + hw;
    const float* ap = la + (size_t)n * NC * HWPIX + hw;

    float rb[NC];
#pragma unroll
    for (int c = 0; c < NC; c++)
        rb[c] = __ldcs(bp + (size_t)c * HWPIX);

    float mb = rb[0];
    int a0 = 0;
#pragma unroll
    for (int c = 1; c < NC; c++)
        if (rb[c] > mb) { mb = rb[c]; a0 = c; }

    float Sb = 0.f, dot = 0.f, Sa = 0.f, le = 0.f;
#pragma unroll
    for (int c = 0; c < NC; c++) {
        float a = __ldcs(ap + (size_t)c * HWPIX);
        float eb = __expf(rb[c]);
        Sb += eb;
        dot = fmaf(eb, a, dot);
        float ea = __expf(a);
        Sa += ea;
        le = (c == a0) ? ea : le;
    }

    float conf = __fdividef(__expf(mb), Sb);
    float w = 1.0f - __fdividef(le, Sa);
    float ce = __logf(Sa) - __fdividef(dot, Sb);

    unsigned int v = min(__float_as_uint(conf) - KBASE, VMAX);
    g_kl[p] = (v << 5) | (unsigned)a0;
    g_loss[p] = w * ce;

    int* h0 = g_hist + (blockIdx.x & (RQ - 1)) * HQ_CLS;
    atomicAdd(&h0[a0 * NBQ + (int)(v >> 13)], 1);
}

// ---------------------------------------------------------------------------
// Per-class quantile select (device fn, blocks 0..18 of reduce kernel).
// The class histogram (5120 bins x 4 replicas) is staged into SHARED with
// fully coalesced stride-256 loads; all scanning then runs on shared.
__device__ void selectq_class(const float* __restrict__ cls_thresh,
                              int c, int* s_bin, int* s_scan, int* s_win)
{
    int t = threadIdx.x;
    const int* hist = g_hist + c * NBQ;

    // Coalesced staging: bin b = j*256 + t, replicas summed on the fly.
#pragma unroll
    for (int j = 0; j < BPQ; j++) {
        int b = j * 256 + t;
        s_bin[b] = hist[b] + hist[HQ_CLS + b]
                 + hist[2 * HQ_CLS + b] + hist[3 * HQ_CLS + b];
    }
    __syncthreads();

    float thr = cls_thresh[c];
    unsigned int tk = __float_as_uint(thr);
    unsigned int tv = (tk >= KBASE) ? min(tk - KBASE, VMAX) : 0u;
    int tbin = (int)(tv >> 13);

    // Stage A: contiguous 20-bin chunk sums from shared
    int b0 = t * BPQ;
    int csum = 0;
#pragma unroll
    for (int i = 0; i < BPQ; i++) csum += s_bin[b0 + i];
    if (tbin >= b0 && tbin < b0 + BPQ) csum++;          // fold threshold elem

    s_scan[t] = csum;
    __syncthreads();
    for (int off = 1; off < 256; off <<= 1) {           // suffix sum
        int v = s_scan[t];
        int add = (t + off < 256) ? s_scan[t + off] : 0;
        __syncthreads();
        s_scan[t] = v + add;
        __syncthreads();
    }

    int total = s_scan[0];                               // == count + 1
    int k = (int)floorf((float)total * ADAPT_B * powf(thr, 8.0f));
    int hi = s_scan[t] - csum;                           // strictly above
    if (k >= hi && k < hi + csum) { s_win[0] = t; s_win[1] = k - hi; }
    __syncthreads();

    // Stage B: walk the winning chunk's 20 bins (thread 0, all in shared)
    if (t == 0) {
        int wc = s_win[0], kk = s_win[1];
        int cum = 0, sel = wc * BPQ;
        for (int i = BPQ - 1; i >= 0; i--) {
            int bin = wc * BPQ + i;
            int bc = s_bin[bin] + ((tbin == bin) ? 1 : 0);
            if (cum + bc > kk) { sel = bin; break; }
            cum += bc;
        }
        unsigned int key = KBASE + ((unsigned)sel << 13);
        float tmp = __uint_as_float(key);                // bin lower edge
        float nt = ADAPT_A * thr + (1.0f - ADAPT_A) * tmp;
        if (nt >= 1.0f) nt = 0.999f;
        g_newth[c] = nt;
    }
    __syncthreads();
}

// ---------------------------------------------------------------------------
// Fused select + masked reduction + finalize + state rezero.
// Blocks 0..18 run select for their class, then flag via g_selcnt.
// All blocks issue data loads + threshold-independent work first, spin on the
// flag (sub-us now that select is ~2us), then apply the mask.
__global__ __launch_bounds__(256, 4) void reduce_kernel(
    const float* __restrict__ ct, float* __restrict__ out, int out_size)
{
    __shared__ int s_bin[NBQ];             // 20 KB staging (select blocks)
    __shared__ int s_scan[256];
    __shared__ int s_win[2];
    __shared__ unsigned int s_th[NC];      // threshold in key-offset space

    int tid = blockIdx.x * blockDim.x + threadIdx.x;

    // ---- threshold-independent data fetch (overlaps select latency) ----
    int i0 = tid * 2;                      // 2 quads; RGRID*256*2 == TPIX/4
    uint4 ka = ((const uint4*)g_kl)[i0];
    uint4 kb = ((const uint4*)g_kl)[i0 + 1];
    float4 va = ((const float4*)g_loss)[i0];
    float4 vb = ((const float4*)g_loss)[i0 + 1];
    unsigned int ks[8] = {ka.x, ka.y, ka.z, ka.w, kb.x, kb.y, kb.z, kb.w};
    float vs[8] = {va.x, va.y, va.z, va.w, vb.x, vb.y, vb.z, vb.w};

    int cs = 0;
#pragma unroll
    for (int j = 0; j < 8; j++)
        if ((ks[j] >> 5) > SOLID_OFF) cs++;

    // ---- producer role: per-class select ----
    if (blockIdx.x < NC) {
        selectq_class(ct, blockIdx.x, s_bin, s_scan, s_win);
        if (threadIdx.x == 0) {
            __threadfence();
            atomicAdd(&g_selcnt, 1u);
        }
    }

    // ---- wait for all 19 selects ----
    if (threadIdx.x == 0) {
        while (*((volatile unsigned int*)&g_selcnt) < NC) __nanosleep(64);
    }
    __syncthreads();
    __threadfence();                        // acquire
    if (threadIdx.x < NC)
        s_th[threadIdx.x] = __float_as_uint(g_newth[threadIdx.x]) - KBASE;
    __syncthreads();

    // hist rezero (all selects done -> safe; restores the invariant)
    {
        int stride = RGRID * 256 * 4;
        for (int i = tid * 4; i < HQ_SZ; i += stride)
            *(int4*)&g_hist[i] = make_int4(0, 0, 0, 0);
    }

    // ---- masked compute ----
    float num = 0.f;
    int cm = 0;
#pragma unroll
    for (int j = 0; j < 8; j++) {
        unsigned int v = ks[j] >> 5;
        int c = (int)(ks[j] & 31u);
        if (v > s_th[c]) { num += fmaxf(vs[j], MIN_EPS); cm++; }
    }

    for (int o = 16; o > 0; o >>= 1) {
        num += __shfl_down_sync(0xffffffffu, num, o);
        cm  += __shfl_down_sync(0xffffffffu, cm, o);
        cs  += __shfl_down_sync(0xffffffffu, cs, o);
    }
    __shared__ float s_num[8];
    __shared__ int s_cm[8], s_cs[8];
    int wid = threadIdx.x >> 5, lid = threadIdx.x & 31;
    if (lid == 0) { s_num[wid] = num; s_cm[wid] = cm; s_cs[wid] = cs; }
    __syncthreads();
    if (wid == 0) {
        num = (lid < 8) ? s_num[lid] : 0.f;
        cm  = (lid < 8) ? s_cm[lid] : 0;
        cs  = (lid < 8) ? s_cs[lid] : 0;
        for (int o = 4; o > 0; o >>= 1) {
            num += __shfl_down_sync(0xffffffffu, num, o);
            cm  += __shfl_down_sync(0xffffffffu, cm, o);
            cs  += __shfl_down_sync(0xffffffffu, cs, o);
        }
        if (lid == 0) {
            atomicAdd(&g_num, (double)num);
            atomicAdd(&g_cm, (unsigned long long)cm);
            atomicAdd(&g_cs, (unsigned long long)cs);
            __threadfence();
            unsigned int old = atomicAdd(&g_done, 1u);
            if (old == gridDim.x - 1) {          // last block finalizes
                double den = (g_cm > 0ull) ? (double)g_cm : 1.0;
                if (out_size > 0) out[0] = (float)(g_num / den);
                if (out_size > 1) out[1] = (float)((double)g_cm / (double)TPIX);
                if (out_size > 2) out[2] = (float)((double)g_cs / (double)TPIX);
                // restore the zero invariant for the next invocation
                g_num = 0.0; g_cm = 0ull; g_cs = 0ull; g_selcnt = 0u;
                __threadfence();
                g_done = 0u;
            }
        }
    }
}

// ---------------------------------------------------------------------------
extern "C" void kernel_launch(void* const* d_in, const int* in_sizes, int n_in,
                              void* d_out, int out_size)
{
    const float* lb = (const float*)d_in[0];
    const float* la = (const float*)d_in[1];
    const float* ct = (const float*)d_in[2];
    float* out = (float*)d_out;

    pass1_kernel<<<TPIX / 256, 256>>>(lb, la);
    reduce_kernel<<<RGRID, 256>>>(ct, out, out_size);
}